// round 14
// baseline (speedup 1.0000x reference)
#include <cuda_runtime.h>
#include <cuda_fp16.h>
#include <cstdint>
#include <cstddef>

// ---------------- problem constants ----------------
#define NB 4096
#define CORE_RSTRIDE 2097152   // 512*512*8 elements (r stride)
#define SEG_FLOATS   16777216  // 8 * CORE_RSTRIDE

// ---------------- scratch (device globals) ----------------
__device__ __half g_Gh[4ull * SEG_FLOATS];   // fp16 copy of G (128 MB)
__device__ float g_xT[2048 * 4096];          // xT[d][b]  (32 MB)
__device__ float g_Gsum[4 * 8 * 4096];
__device__ float g_S[4 * NB * 64];
__device__ float g_env[4 * NB * 64];

// ---------------- helpers ----------------
__device__ __forceinline__ uint32_t h2pack(float hi, float lo) {
    uint32_t d;
    asm("cvt.rn.f16x2.f32 %0, %1, %2;\n" : "=r"(d) : "f"(hi), "f"(lo));
    return d;
}
__device__ __forceinline__ void cpa16(uint32_t saddr, const void* g) {
    asm volatile("cp.async.cg.shared.global [%0], [%1], 16;\n" :: "r"(saddr), "l"(g) : "memory");
}
__device__ __forceinline__ void mma_f16(float* c, const uint32_t* a, const uint32_t* b) {
    asm volatile(
        "mma.sync.aligned.m16n8k16.row.col.f32.f16.f16.f32 "
        "{%0,%1,%2,%3}, {%4,%5,%6,%7}, {%8,%9}, {%0,%1,%2,%3};\n"
        : "+f"(c[0]), "+f"(c[1]), "+f"(c[2]), "+f"(c[3])
        : "r"(a[0]), "r"(a[1]), "r"(a[2]), "r"(a[3]), "r"(b[0]), "r"(b[1]));
}
__device__ __forceinline__ void ldmx4(uint32_t& d0, uint32_t& d1, uint32_t& d2, uint32_t& d3,
                                      uint32_t addr) {
    asm volatile("ldmatrix.sync.aligned.m8n8.x4.shared.b16 {%0,%1,%2,%3}, [%4];"
                 : "=r"(d0), "=r"(d1), "=r"(d2), "=r"(d3) : "r"(addr));
}

// ================= kernel 0: convert G -> fp16 AND reduce over o (fused) =============
// grid (16 xsblk, 8 r, 4 seg), 256 threads. Each thread: one xs, loop 512 o.
__global__ void k_half_gsum(const float* __restrict__ c0, const float* __restrict__ c1,
                            const float* __restrict__ c2, const float* __restrict__ c3) {
    int seg = blockIdx.z, r = blockIdx.y;
    const float* G = (seg == 0) ? c0 : (seg == 1) ? c1 : (seg == 2) ? c2 : c3;
    __half* Gh = g_Gh + (size_t)seg * SEG_FLOATS;
    int xs = blockIdx.x * 256 + threadIdx.x;
    size_t base = (size_t)r * CORE_RSTRIDE + xs;
    float acc = 0.f;
#pragma unroll 4
    for (int o = 0; o < 512; o++) {
        size_t off = base + (size_t)o * 4096;
        float v = G[off];
        acc += v;
        Gh[off] = __float2half_rn(v);
    }
    g_Gsum[(size_t)(seg * 8 + r) * 4096 + xs] = acc;
}

// ================= kernel 1: transpose x =================
__global__ void k_transpose(const float* __restrict__ x) {
    __shared__ float tile[32][33];
    int d0 = blockIdx.x * 32, b0 = blockIdx.y * 32;
    int tx = threadIdx.x, ty = threadIdx.y;
#pragma unroll
    for (int j = 0; j < 32; j += 8)
        tile[ty + j][tx] = x[(size_t)(b0 + ty + j) * 2048 + d0 + tx];
    __syncthreads();
#pragma unroll
    for (int j = 0; j < 32; j += 8)
        g_xT[(size_t)(d0 + ty + j) * 4096 + b0 + tx] = tile[tx][ty + j];
}

// ================= kernel 3: S (register-blocked, via xT) =================
// S[seg][b][r*8+s] = sum_xc Gsum[seg][r][xc*8+s] * xT[seg*512+xc][b]
// grid (32 bblk, 4 seg), 256 threads: r = t>>5 (8), bg = t&31; 4 b per thread.
__global__ void k_S2() {
    int seg = blockIdx.y;
    int b0 = blockIdx.x * 128;
    int t = threadIdx.x;
    int r = t >> 5, bg = t & 31;
    const float4* gp = (const float4*)(g_Gsum + (size_t)(seg * 8 + r) * 4096);
    const float* xbase = g_xT + (size_t)(seg * 512) * 4096 + b0 + bg * 4;

    float acc[8][4];
#pragma unroll
    for (int s = 0; s < 8; s++)
#pragma unroll
        for (int j = 0; j < 4; j++) acc[s][j] = 0.f;

#pragma unroll 2
    for (int xc = 0; xc < 512; xc++) {
        float4 ga = gp[xc * 2], gb = gp[xc * 2 + 1];
        float4 xv = *(const float4*)(xbase + (size_t)xc * 4096);
        float gs[8] = {ga.x, ga.y, ga.z, ga.w, gb.x, gb.y, gb.z, gb.w};
        float xa[4] = {xv.x, xv.y, xv.z, xv.w};
#pragma unroll
        for (int s = 0; s < 8; s++)
#pragma unroll
            for (int j = 0; j < 4; j++) acc[s][j] += gs[s] * xa[j];
    }
#pragma unroll
    for (int j = 0; j < 4; j++) {
        int b = b0 + bg * 4 + j;
        float4 lo = {acc[0][j], acc[1][j], acc[2][j], acc[3][j]};
        float4 hi = {acc[4][j], acc[5][j], acc[6][j], acc[7][j]};
        *(float4*)(g_S + (size_t)(seg * NB + b) * 64 + r * 8)     = lo;
        *(float4*)(g_S + (size_t)(seg * NB + b) * 64 + r * 8 + 4) = hi;
    }
}

// ================= kernel 4: ring products -> env =================
__global__ void k_env() {
    int b = blockIdx.x, t = threadIdx.x;
    int r = t >> 3, c = t & 7;
    __shared__ float Sm[4][64], P2[64], P3[64], Q1[64], Q0[64], E[64];
#pragma unroll
    for (int i = 0; i < 4; i++) Sm[i][t] = g_S[(size_t)(i * NB + b) * 64 + t];
    __syncthreads();
    float v;
    v = 0.f;
#pragma unroll
    for (int k = 0; k < 8; k++) v += Sm[0][r * 8 + k] * Sm[1][k * 8 + c];
    P2[t] = v;
    v = 0.f;
#pragma unroll
    for (int k = 0; k < 8; k++) v += Sm[2][r * 8 + k] * Sm[3][k * 8 + c];
    Q1[t] = v;
    __syncthreads();
    v = 0.f;
#pragma unroll
    for (int k = 0; k < 8; k++) v += P2[r * 8 + k] * Sm[2][k * 8 + c];
    P3[t] = v;
    v = 0.f;
#pragma unroll
    for (int k = 0; k < 8; k++) v += Sm[1][r * 8 + k] * Q1[k * 8 + c];
    Q0[t] = v;
    __syncthreads();
    g_env[(size_t)(0 * NB + b) * 64 + t] = Q0[c * 8 + r];
    g_env[(size_t)(3 * NB + b) * 64 + t] = P3[c * 8 + r];
    v = 0.f;
#pragma unroll
    for (int k = 0; k < 8; k++) v += Q1[r * 8 + k] * Sm[0][k * 8 + c];
    E[t] = v;
    __syncthreads();
    g_env[(size_t)(1 * NB + b) * 64 + t] = E[c * 8 + r];
    __syncthreads();
    v = 0.f;
#pragma unroll
    for (int k = 0; k < 8; k++) v += Sm[3][r * 8 + k] * P2[k * 8 + c];
    E[t] = v;
    __syncthreads();
    g_env[(size_t)(2 * NB + b) * 64 + t] = E[c * 8 + r];
}

// ================= kernel 5: main GEMM (fp16 m16n8k16 + ldmatrix B) =================
// CTA 128(M=b) x 128(N=o), 128 threads (2x2 warps, warp tile 64x64).
// Stage: K=64 (8 x-values, 4 k16 chunks). 512 stages total.
#define STAGES 4
#define BS_STAGE   18432       // 128 rows * 144 B (64 halfs + pad)
#define XCH_BASE   73728
#define XCH_STAGE  4224
#define XCH_ROW_F  132
#define GEMM_SMEM  (XCH_BASE + STAGES * XCH_STAGE)

__global__ void __launch_bounds__(128, 2) k_gemm(
    const float* __restrict__ bias, float* __restrict__ out) {
    extern __shared__ char sm[];
    float* smf = (float*)sm;
    uint32_t sb = (uint32_t)__cvta_generic_to_shared(sm);

    int seg = blockIdx.z;
    int o0 = blockIdx.x * 128;
    int b0 = blockIdx.y * 128;
    int t = threadIdx.x;
    int warp = t >> 5, lane = t & 31;
    int g = lane >> 2, tg = lane & 3;
    int mW = (warp >> 1) * 64, nW = (warp & 1) * 64;

    const __half* Ghseg = g_Gh + (size_t)seg * SEG_FLOATS;
    const float*  xTseg = g_xT + (size_t)seg * 512 * 4096 + b0;

    auto issue = [&](int s) {
        int buf = s & (STAGES - 1);
        int r = s >> 6, stx = s & 63;
        const __half* Gr = Ghseg + (size_t)r * CORE_RSTRIDE + (size_t)o0 * 4096 + stx * 64;
        uint32_t bst = sb + buf * BS_STAGE;
#pragma unroll
        for (int j = 0; j < 8; j++) {
            int idx = j * 128 + t;
            int row = idx >> 3, col = idx & 7;
            cpa16(bst + row * 144 + col * 16, Gr + (size_t)row * 4096 + col * 8);
        }
#pragma unroll
        for (int j = 0; j < 2; j++) {
            int idx = j * 128 + t;
            int xl = idx >> 5, c = idx & 31;
            cpa16(sb + XCH_BASE + buf * XCH_STAGE + xl * 528 + c * 16,
                  xTseg + (size_t)(stx * 8 + xl) * 4096 + c * 4);
        }
    };

    float acc[4][8][4];
#pragma unroll
    for (int a = 0; a < 4; a++)
#pragma unroll
        for (int b = 0; b < 8; b++)
#pragma unroll
            for (int c = 0; c < 4; c++) acc[a][b][c] = 0.f;

    int b_of[8];
#pragma unroll
    for (int j = 0; j < 8; j++) b_of[j] = mW + g + j * 8;

    // ldmatrix per-thread base offsets: 4 matrices per op, np covers nf pair (2np, 2np+1)
    int lq = lane >> 3, lj = lane & 7;
    uint32_t lm_off[4];
#pragma unroll
    for (int np = 0; np < 4; np++)
        lm_off[np] = (uint32_t)((nW + np * 16 + (lq >> 1) * 8 + lj) * 144 + (lq & 1) * 16);

#pragma unroll
    for (int s = 0; s < STAGES - 1; s++) {
        issue(s);
        asm volatile("cp.async.commit_group;\n" ::: "memory");
    }

    float e0[8], e1[8];

    for (int s = 0; s < 512; s++) {
        if ((s & 63) == 0) {
            int r = s >> 6;
            const float* ep = g_env + (size_t)(seg * NB + b0) * 64 + r * 8 + 2 * tg;
#pragma unroll
            for (int j = 0; j < 8; j++) {
                float2 e = *(const float2*)(ep + (size_t)b_of[j] * 64);
                e0[j] = e.x; e1[j] = e.y;
            }
        }
        asm volatile("cp.async.wait_group 2;\n" ::: "memory");
        __syncthreads();
        int nxt = s + STAGES - 1;
        if (nxt < 512) issue(nxt);
        asm volatile("cp.async.commit_group;\n" ::: "memory");

        int buf = s & (STAGES - 1);
        const float* xbuf = smf + (XCH_BASE + buf * XCH_STAGE) / 4;
        uint32_t bst = sb + buf * BS_STAGE;

#pragma unroll
        for (int ch = 0; ch < 4; ch++) {
            const float* xr0 = xbuf + (2 * ch) * XCH_ROW_F;
            const float* xr1 = xbuf + (2 * ch + 1) * XCH_ROW_F;
            float xv0[8], xv1[8];
#pragma unroll
            for (int j = 0; j < 8; j++) { xv0[j] = xr0[b_of[j]]; xv1[j] = xr1[b_of[j]]; }

            // B fragments via ldmatrix.x4 (2 nf per op)
            uint32_t bf[8][2];
#pragma unroll
            for (int np = 0; np < 4; np++)
                ldmx4(bf[2 * np][0], bf[2 * np][1], bf[2 * np + 1][0], bf[2 * np + 1][1],
                      bst + lm_off[np] + ch * 32);

            uint32_t a[4][4];
#pragma unroll
            for (int mf = 0; mf < 4; mf++) {
                int jl = 2 * mf, jh = 2 * mf + 1;
                a[mf][0] = h2pack(xv0[jl] * e1[jl], xv0[jl] * e0[jl]);
                a[mf][1] = h2pack(xv0[jh] * e1[jh], xv0[jh] * e0[jh]);
                a[mf][2] = h2pack(xv1[jl] * e1[jl], xv1[jl] * e0[jl]);
                a[mf][3] = h2pack(xv1[jh] * e1[jh], xv1[jh] * e0[jh]);
            }
#pragma unroll
            for (int nf = 0; nf < 8; nf++)
#pragma unroll
                for (int mf = 0; mf < 4; mf++)
                    mma_f16(acc[mf][nf], a[mf], bf[nf]);
        }
    }
    __syncthreads();

    // epilogue
    int row0 = b0 + mW + g;
    int cbase = seg * 512 + o0 + nW;
#pragma unroll
    for (int mf = 0; mf < 4; mf++) {
#pragma unroll
        for (int nf = 0; nf < 8; nf++) {
            int col = cbase + nf * 8 + tg * 2;
            float2 bv = *(const float2*)&bias[col];
            int ra = row0 + mf * 16;
            float2 v0 = {acc[mf][nf][0] + bv.x, acc[mf][nf][1] + bv.y};
            float2 v1 = {acc[mf][nf][2] + bv.x, acc[mf][nf][3] + bv.y};
            *(float2*)&out[(size_t)ra * 2048 + col]       = v0;
            *(float2*)&out[(size_t)(ra + 8) * 2048 + col] = v1;
        }
    }
}

// ================= launch =================
extern "C" void kernel_launch(void* const* d_in, const int* in_sizes, int n_in,
                              void* d_out, int out_size) {
    (void)in_sizes; (void)n_in; (void)out_size;
    const float* x    = (const float*)d_in[0];
    const float* c0   = (const float*)d_in[1];
    const float* c1   = (const float*)d_in[2];
    const float* c2   = (const float*)d_in[3];
    const float* c3   = (const float*)d_in[4];
    const float* bias = (const float*)d_in[5];
    float* out = (float*)d_out;

    cudaFuncSetAttribute(k_gemm, cudaFuncAttributeMaxDynamicSharedMemorySize, GEMM_SMEM);

    k_half_gsum<<<dim3(16, 8, 4), 256>>>(c0, c1, c2, c3);
    k_transpose<<<dim3(64, 128), dim3(32, 8)>>>(x);
    k_S2<<<dim3(32, 4), 256>>>();
    k_env<<<4096, 64>>>();
    k_gemm<<<dim3(4, 32, 4), 128, GEMM_SMEM>>>(bias, out);
}

// round 15
// speedup vs baseline: 1.0449x; 1.0449x over previous
#include <cuda_runtime.h>
#include <cuda_fp16.h>
#include <cstdint>
#include <cstddef>

// ---------------- problem constants ----------------
#define NB 4096
#define CORE_RSTRIDE 2097152   // 512*512*8 elements (r stride)
#define SEG_FLOATS   16777216  // 8 * CORE_RSTRIDE

// ---------------- scratch (device globals) ----------------
__device__ __half g_Gh[4ull * SEG_FLOATS];   // fp16 copy of G (128 MB)
__device__ float g_xT[2048 * 4096];          // xT[d][b]  (32 MB)
__device__ float g_Gsum[4 * 8 * 4096];
__device__ float g_S[4 * NB * 64];
__device__ float g_env[4 * NB * 64];

// ---------------- helpers ----------------
__device__ __forceinline__ uint32_t h2pack(float hi, float lo) {
    uint32_t d;
    asm("cvt.rn.f16x2.f32 %0, %1, %2;\n" : "=r"(d) : "f"(hi), "f"(lo));
    return d;
}
__device__ __forceinline__ void cpa16(uint32_t saddr, const void* g) {
    asm volatile("cp.async.cg.shared.global [%0], [%1], 16;\n" :: "r"(saddr), "l"(g) : "memory");
}
__device__ __forceinline__ void mma_f16(float* c, const uint32_t* a, const uint32_t* b) {
    asm volatile(
        "mma.sync.aligned.m16n8k16.row.col.f32.f16.f16.f32 "
        "{%0,%1,%2,%3}, {%4,%5,%6,%7}, {%8,%9}, {%0,%1,%2,%3};\n"
        : "+f"(c[0]), "+f"(c[1]), "+f"(c[2]), "+f"(c[3])
        : "r"(a[0]), "r"(a[1]), "r"(a[2]), "r"(a[3]), "r"(b[0]), "r"(b[1]));
}

// ================= kernel 0: convert G -> fp16 AND reduce over o (fused) =============
__global__ void k_half_gsum(const float* __restrict__ c0, const float* __restrict__ c1,
                            const float* __restrict__ c2, const float* __restrict__ c3) {
    int seg = blockIdx.z, r = blockIdx.y;
    const float* G = (seg == 0) ? c0 : (seg == 1) ? c1 : (seg == 2) ? c2 : c3;
    __half* Gh = g_Gh + (size_t)seg * SEG_FLOATS;
    int xs = blockIdx.x * 256 + threadIdx.x;
    size_t base = (size_t)r * CORE_RSTRIDE + xs;
    float acc = 0.f;
#pragma unroll 4
    for (int o = 0; o < 512; o++) {
        size_t off = base + (size_t)o * 4096;
        float v = G[off];
        acc += v;
        Gh[off] = __float2half_rn(v);
    }
    g_Gsum[(size_t)(seg * 8 + r) * 4096 + xs] = acc;
}

// ================= kernel 1: transpose x =================
__global__ void k_transpose(const float* __restrict__ x) {
    __shared__ float tile[32][33];
    int d0 = blockIdx.x * 32, b0 = blockIdx.y * 32;
    int tx = threadIdx.x, ty = threadIdx.y;
#pragma unroll
    for (int j = 0; j < 32; j += 8)
        tile[ty + j][tx] = x[(size_t)(b0 + ty + j) * 2048 + d0 + tx];
    __syncthreads();
#pragma unroll
    for (int j = 0; j < 32; j += 8)
        g_xT[(size_t)(d0 + ty + j) * 4096 + b0 + tx] = tile[tx][ty + j];
}

// ================= kernel 3: S (register-blocked, via xT) =================
__global__ void k_S2() {
    int seg = blockIdx.y;
    int b0 = blockIdx.x * 128;
    int t = threadIdx.x;
    int r = t >> 5, bg = t & 31;
    const float4* gp = (const float4*)(g_Gsum + (size_t)(seg * 8 + r) * 4096);
    const float* xbase = g_xT + (size_t)(seg * 512) * 4096 + b0 + bg * 4;

    float acc[8][4];
#pragma unroll
    for (int s = 0; s < 8; s++)
#pragma unroll
        for (int j = 0; j < 4; j++) acc[s][j] = 0.f;

#pragma unroll 2
    for (int xc = 0; xc < 512; xc++) {
        float4 ga = gp[xc * 2], gb = gp[xc * 2 + 1];
        float4 xv = *(const float4*)(xbase + (size_t)xc * 4096);
        float gs[8] = {ga.x, ga.y, ga.z, ga.w, gb.x, gb.y, gb.z, gb.w};
        float xa[4] = {xv.x, xv.y, xv.z, xv.w};
#pragma unroll
        for (int s = 0; s < 8; s++)
#pragma unroll
            for (int j = 0; j < 4; j++) acc[s][j] += gs[s] * xa[j];
    }
#pragma unroll
    for (int j = 0; j < 4; j++) {
        int b = b0 + bg * 4 + j;
        float4 lo = {acc[0][j], acc[1][j], acc[2][j], acc[3][j]};
        float4 hi = {acc[4][j], acc[5][j], acc[6][j], acc[7][j]};
        *(float4*)(g_S + (size_t)(seg * NB + b) * 64 + r * 8)     = lo;
        *(float4*)(g_S + (size_t)(seg * NB + b) * 64 + r * 8 + 4) = hi;
    }
}

// ================= kernel 4: ring products -> env =================
__global__ void k_env() {
    int b = blockIdx.x, t = threadIdx.x;
    int r = t >> 3, c = t & 7;
    __shared__ float Sm[4][64], P2[64], P3[64], Q1[64], Q0[64], E[64];
#pragma unroll
    for (int i = 0; i < 4; i++) Sm[i][t] = g_S[(size_t)(i * NB + b) * 64 + t];
    __syncthreads();
    float v;
    v = 0.f;
#pragma unroll
    for (int k = 0; k < 8; k++) v += Sm[0][r * 8 + k] * Sm[1][k * 8 + c];
    P2[t] = v;
    v = 0.f;
#pragma unroll
    for (int k = 0; k < 8; k++) v += Sm[2][r * 8 + k] * Sm[3][k * 8 + c];
    Q1[t] = v;
    __syncthreads();
    v = 0.f;
#pragma unroll
    for (int k = 0; k < 8; k++) v += P2[r * 8 + k] * Sm[2][k * 8 + c];
    P3[t] = v;
    v = 0.f;
#pragma unroll
    for (int k = 0; k < 8; k++) v += Sm[1][r * 8 + k] * Q1[k * 8 + c];
    Q0[t] = v;
    __syncthreads();
    g_env[(size_t)(0 * NB + b) * 64 + t] = Q0[c * 8 + r];
    g_env[(size_t)(3 * NB + b) * 64 + t] = P3[c * 8 + r];
    v = 0.f;
#pragma unroll
    for (int k = 0; k < 8; k++) v += Q1[r * 8 + k] * Sm[0][k * 8 + c];
    E[t] = v;
    __syncthreads();
    g_env[(size_t)(1 * NB + b) * 64 + t] = E[c * 8 + r];
    __syncthreads();
    v = 0.f;
#pragma unroll
    for (int k = 0; k < 8; k++) v += Sm[3][r * 8 + k] * P2[k * 8 + c];
    E[t] = v;
    __syncthreads();
    g_env[(size_t)(2 * NB + b) * 64 + t] = E[c * 8 + r];
}

// ================= kernel 5: main GEMM (fp16 m16n8k16, direct LDS) =================
// CTA 128(M=b) x 128(N=o), 128 threads (2x2 warps, warp tile 64x64).
// Stage: K=64 (8 x-values, 4 k16 chunks). 512 stages total.
#define STAGES 4
#define BS_STAGE   18432       // 128 rows * 144 B (64 halfs + pad)
#define BS_ROW_W   36          // words per B row
#define XCH_BASE   73728
#define XCH_STAGE  4224
#define XCH_ROW_F  132
#define GEMM_SMEM  (XCH_BASE + STAGES * XCH_STAGE)

__global__ void __launch_bounds__(128, 2) k_gemm(
    const float* __restrict__ bias, float* __restrict__ out) {
    extern __shared__ char sm[];
    float* smf = (float*)sm;
    uint32_t* smw = (uint32_t*)sm;
    uint32_t sb = (uint32_t)__cvta_generic_to_shared(sm);

    int seg = blockIdx.z;
    int o0 = blockIdx.x * 128;
    int b0 = blockIdx.y * 128;
    int t = threadIdx.x;
    int warp = t >> 5, lane = t & 31;
    int g = lane >> 2, tg = lane & 3;
    int mW = (warp >> 1) * 64, nW = (warp & 1) * 64;

    const __half* Ghseg = g_Gh + (size_t)seg * SEG_FLOATS;
    const float*  xTseg = g_xT + (size_t)seg * 512 * 4096 + b0;

    auto issue = [&](int s) {
        int buf = s & (STAGES - 1);
        int r = s >> 6, stx = s & 63;
        const __half* Gr = Ghseg + (size_t)r * CORE_RSTRIDE + (size_t)o0 * 4096 + stx * 64;
        uint32_t bst = sb + buf * BS_STAGE;
#pragma unroll
        for (int j = 0; j < 8; j++) {
            int idx = j * 128 + t;
            int row = idx >> 3, col = idx & 7;
            cpa16(bst + row * 144 + col * 16, Gr + (size_t)row * 4096 + col * 8);
        }
#pragma unroll
        for (int j = 0; j < 2; j++) {
            int idx = j * 128 + t;
            int xl = idx >> 5, c = idx & 31;
            cpa16(sb + XCH_BASE + buf * XCH_STAGE + xl * 528 + c * 16,
                  xTseg + (size_t)(stx * 8 + xl) * 4096 + c * 4);
        }
    };

    float acc[4][8][4];
#pragma unroll
    for (int a = 0; a < 4; a++)
#pragma unroll
        for (int b = 0; b < 8; b++)
#pragma unroll
            for (int c = 0; c < 4; c++) acc[a][b][c] = 0.f;

    int b_of[8];
#pragma unroll
    for (int j = 0; j < 8; j++) b_of[j] = mW + g + j * 8;

#pragma unroll
    for (int s = 0; s < STAGES - 1; s++) {
        issue(s);
        asm volatile("cp.async.commit_group;\n" ::: "memory");
    }

    float e0[8], e1[8];

    for (int s = 0; s < 512; s++) {
        if ((s & 63) == 0) {
            int r = s >> 6;
            const float* ep = g_env + (size_t)(seg * NB + b0) * 64 + r * 8 + 2 * tg;
#pragma unroll
            for (int j = 0; j < 8; j++) {
                float2 e = *(const float2*)(ep + (size_t)b_of[j] * 64);
                e0[j] = e.x; e1[j] = e.y;
            }
        }
        asm volatile("cp.async.wait_group 2;\n" ::: "memory");
        __syncthreads();
        int nxt = s + STAGES - 1;
        if (nxt < 512) issue(nxt);
        asm volatile("cp.async.commit_group;\n" ::: "memory");

        int buf = s & (STAGES - 1);
        const float* xbuf = smf + (XCH_BASE + buf * XCH_STAGE) / 4;
        const uint32_t* bbuf = smw + (buf * BS_STAGE) / 4;

#pragma unroll
        for (int ch = 0; ch < 4; ch++) {
            const float* xr0 = xbuf + (2 * ch) * XCH_ROW_F;
            const float* xr1 = xbuf + (2 * ch + 1) * XCH_ROW_F;
            float xv0[8], xv1[8];
#pragma unroll
            for (int j = 0; j < 8; j++) { xv0[j] = xr0[b_of[j]]; xv1[j] = xr1[b_of[j]]; }

            uint32_t a[4][4];
#pragma unroll
            for (int mf = 0; mf < 4; mf++) {
                int jl = 2 * mf, jh = 2 * mf + 1;
                a[mf][0] = h2pack(xv0[jl] * e1[jl], xv0[jl] * e0[jl]);
                a[mf][1] = h2pack(xv0[jh] * e1[jh], xv0[jh] * e0[jh]);
                a[mf][2] = h2pack(xv1[jl] * e1[jl], xv1[jl] * e0[jl]);
                a[mf][3] = h2pack(xv1[jh] * e1[jh], xv1[jh] * e0[jh]);
            }
#pragma unroll
            for (int nf = 0; nf < 8; nf++) {
                int row = nW + nf * 8 + g;
                uint32_t bb[2];
                bb[0] = bbuf[row * BS_ROW_W + ch * 8 + tg];
                bb[1] = bbuf[row * BS_ROW_W + ch * 8 + tg + 4];
#pragma unroll
                for (int mf = 0; mf < 4; mf++)
                    mma_f16(acc[mf][nf], a[mf], bb);
            }
        }
    }
    __syncthreads();

    // epilogue
    int row0 = b0 + mW + g;
    int cbase = seg * 512 + o0 + nW;
#pragma unroll
    for (int mf = 0; mf < 4; mf++) {
#pragma unroll
        for (int nf = 0; nf < 8; nf++) {
            int col = cbase + nf * 8 + tg * 2;
            float2 bv = *(const float2*)&bias[col];
            int ra = row0 + mf * 16;
            float2 v0 = {acc[mf][nf][0] + bv.x, acc[mf][nf][1] + bv.y};
            float2 v1 = {acc[mf][nf][2] + bv.x, acc[mf][nf][3] + bv.y};
            *(float2*)&out[(size_t)ra * 2048 + col]       = v0;
            *(float2*)&out[(size_t)(ra + 8) * 2048 + col] = v1;
        }
    }
}

// ================= launch =================
extern "C" void kernel_launch(void* const* d_in, const int* in_sizes, int n_in,
                              void* d_out, int out_size) {
    (void)in_sizes; (void)n_in; (void)out_size;
    const float* x    = (const float*)d_in[0];
    const float* c0   = (const float*)d_in[1];
    const float* c1   = (const float*)d_in[2];
    const float* c2   = (const float*)d_in[3];
    const float* c3   = (const float*)d_in[4];
    const float* bias = (const float*)d_in[5];
    float* out = (float*)d_out;

    cudaFuncSetAttribute(k_gemm, cudaFuncAttributeMaxDynamicSharedMemorySize, GEMM_SMEM);

    k_half_gsum<<<dim3(16, 8, 4), 256>>>(c0, c1, c2, c3);
    k_transpose<<<dim3(64, 128), dim3(32, 8)>>>(x);
    k_S2<<<dim3(32, 4), 256>>>();
    k_env<<<4096, 64>>>();
    k_gemm<<<dim3(4, 32, 4), 128, GEMM_SMEM>>>(bias, out);
}